// round 9
// baseline (speedup 1.0000x reference)
#include <cuda_runtime.h>
#include <math.h>

#define IMG   112
#define CCH   192
#define NPIX  (32*IMG*IMG)         // 401408 pixels
#define GIMG  8                    // images per pipeline group
#define NGRP  (32/GIMG)            // 4 groups
#define PAIRS_G (GIMG*IMG*IMG/2)   // 50176 pixel-pairs per group
#define TW    28
#define TH    8
#define HALO  3
#define HDW   (TW + 2*HALO)        // 34
#define HDH   (TH + 2*HALO)        // 14
#define NHP   (HDW*HDH)            // 476
#define NT    256
#define NW    (NT/32)              // 8
#define F4    (CCH/4)              // 48

// pooled[pix*2+0]=avg, [pix*2+1]=max  (3.2 MB, L2-resident)
__device__ float g_pooled[NPIX * 2];

__device__ __forceinline__ float hsum(float4 v) { return (v.x + v.y) + (v.z + v.w); }
__device__ __forceinline__ float hmax(float4 v) { return fmaxf(fmaxf(v.x, v.y), fmaxf(v.z, v.w)); }

// ---------------- Kernel A: channel avg/max, 2 pixels per warp ----------------
__global__ __launch_bounds__(NT, 8)
void reduce_kernel(const float* __restrict__ x, int pair0)
{
    const int lane = threadIdx.x & 31;
    const int pair = pair0 + blockIdx.x * NW + (threadIdx.x >> 5);

    const float4* p = reinterpret_cast<const float4*>(x + (size_t)pair * 2 * CCH);
    float4 a0 = __ldcs(p + lane);          // f4 [0,32)   -> pixel 0
    float4 a1 = __ldcs(p + 32 + lane);     // f4 [32,64)  -> px0 (lane<16) / px1 (lane>=16)
    float4 a2 = __ldcs(p + 64 + lane);     // f4 [64,96)  -> pixel 1

    float s0 = hsum(a0), m0 = hmax(a0);
    float s1 = hsum(a2), m1 = hmax(a2);
    float sm = hsum(a1), mm = hmax(a1);
    if (lane < 16) { s0 += sm; m0 = fmaxf(m0, mm); }
    else           { s1 += sm; m1 = fmaxf(m1, mm); }

    #pragma unroll
    for (int o = 16; o > 0; o >>= 1) {
        s0 += __shfl_xor_sync(0xffffffffu, s0, o);
        s1 += __shfl_xor_sync(0xffffffffu, s1, o);
        m0  = fmaxf(m0, __shfl_xor_sync(0xffffffffu, m0, o));
        m1  = fmaxf(m1, __shfl_xor_sync(0xffffffffu, m1, o));
    }
    if (lane == 0) {
        float4 r = make_float4(s0 * (1.0f / CCH), m0, s1 * (1.0f / CCH), m1);
        *reinterpret_cast<float4*>(&g_pooled[(size_t)pair * 4]) = r;
    }
}

// ---------------- Kernel B: conv + sigmoid + apply (fused) ----------------
__global__ __launch_bounds__(NT, 8)
void apply_kernel(const float* __restrict__ x,
                  const float* __restrict__ w,
                  float* __restrict__ out,
                  int b0)
{
    __shared__ float s_avg[NHP];
    __shared__ float s_max[NHP];
    __shared__ float s_att[TW*TH];
    __shared__ float s_w[98];

    const int tid = threadIdx.x;
    if (tid < 98) s_w[tid] = w[tid];

    const int TPX = IMG / TW;                // 4
    const int TPY = IMG / TH;                // 14
    int bidx = blockIdx.x;
    int b    = b0 + bidx / (TPX*TPY);
    int tr   = bidx % (TPX*TPY);
    int ty0  = (tr / TPX) * TH;
    int tx0  = (tr % TPX) * TW;

    // ---- Phase 1: load pooled halo (tiny, L2-hot) ----
    for (int p = tid; p < NHP; p += NT) {
        int hy = ty0 + p / HDW - HALO;
        int wx = tx0 + p % HDW - HALO;
        float a = 0.f, m = 0.f;
        if (hy >= 0 && hy < IMG && wx >= 0 && wx < IMG) {
            size_t pix = ((size_t)b * IMG + hy) * IMG + wx;
            float2 r = *reinterpret_cast<const float2*>(&g_pooled[pix * 2]);
            a = r.x; m = r.y;
        }
        s_avg[p] = a;
        s_max[p] = m;
    }
    __syncthreads();

    // ---- Phase 2: 7x7 conv (cross-correlation) + sigmoid ----
    if (tid < TW*TH) {
        int oy = tid / TW, ox = tid % TW;
        float acc = 0.f;
        #pragma unroll
        for (int kh = 0; kh < 7; kh++) {
            #pragma unroll
            for (int kw = 0; kw < 7; kw++) {
                int p = (oy + kh) * HDW + (ox + kw);
                acc = fmaf(s_avg[p], s_w[(kh*7 + kw)*2 + 0], acc);
                acc = fmaf(s_max[p], s_w[(kh*7 + kw)*2 + 1], acc);
            }
        }
        s_att[tid] = 1.0f / (1.0f + __expf(-acc));
    }
    __syncthreads();

    // ---- Phase 3: out = x * att, float4 streaming, unroll-2 ----
    // total4 = 28*8*48 = 10752 = 21 * (NT*2) -> no remainder
    const int total4 = TW*TH*F4;
    #pragma unroll 1
    for (int k = tid; k < total4; k += NT*2) {
        float4 v[2]; float a[2]; size_t g[2];
        #pragma unroll
        for (int u = 0; u < 2; u++) {
            int kk = k + u*NT;
            int pt = kk / F4;
            int c4 = kk - pt * F4;
            int oy = pt / TW, ox = pt - oy * TW;
            g[u] = (((size_t)b * IMG + (ty0 + oy)) * IMG + (tx0 + ox)) * CCH + (size_t)c4 * 4;
            v[u] = __ldcs(reinterpret_cast<const float4*>(x + g[u]));
            a[u] = s_att[pt];
        }
        #pragma unroll
        for (int u = 0; u < 2; u++) {
            float4 r = v[u]; float s = a[u];
            r.x *= s; r.y *= s; r.z *= s; r.w *= s;
            __stcs(reinterpret_cast<float4*>(out + g[u]), r);
        }
    }
}

extern "C" void kernel_launch(void* const* d_in, const int* in_sizes, int n_in,
                              void* d_out, int out_size)
{
    const float* x = (const float*)d_in[0];
    const float* w = (const float*)d_in[1];
    float* out = (float*)d_out;

    const int TPX = IMG / TW, TPY = IMG / TH;        // 4, 14
    const int RBLK_G = PAIRS_G / NW;                 // 6272
    const int ABLK_G = GIMG * TPX * TPY;             // 448

    // Fork a side stream for the reduce chain so apply(g) can overlap
    // reduce(g+1..). Standard event fork/join, graph-capture legal.
    cudaStream_t s1;
    cudaStreamCreateWithFlags(&s1, cudaStreamNonBlocking);

    cudaEvent_t fork;
    cudaEventCreateWithFlags(&fork, cudaEventDisableTiming);
    cudaEventRecord(fork, 0);                         // on capture (default) stream
    cudaStreamWaitEvent(s1, fork, 0);                 // fork s1 from capture DAG

    cudaEvent_t done[NGRP];
    for (int g = 0; g < NGRP; g++) {
        reduce_kernel<<<RBLK_G, NT, 0, s1>>>(x, g * PAIRS_G);
        cudaEventCreateWithFlags(&done[g], cudaEventDisableTiming);
        cudaEventRecord(done[g], s1);
    }

    for (int g = 0; g < NGRP; g++) {
        cudaStreamWaitEvent(0, done[g], 0);           // apply(g) depends on reduce(g)
        apply_kernel<<<ABLK_G, NT>>>(x, w, out, g * GIMG);
    }
    // waiting on done[NGRP-1] above joined s1 back into the capture stream.

    cudaEventDestroy(fork);
    for (int g = 0; g < NGRP; g++) cudaEventDestroy(done[g]);
    cudaStreamDestroy(s1);
}

// round 10
// speedup vs baseline: 1.0317x; 1.0317x over previous
#include <cuda_runtime.h>
#include <math.h>

#define IMG   112
#define CCH   192
#define NPIX  (32*IMG*IMG)         // 401408 pixels
#define GIMG  8                    // images per group (77 MB x-chunk < 126 MB L2)
#define NGRP  (32/GIMG)            // 4 groups
#define PAIRS_G (GIMG*IMG*IMG/2)   // 50176 pixel-pairs per group
#define TW    28
#define TH    8
#define HALO  3
#define HDW   (TW + 2*HALO)        // 34
#define HDH   (TH + 2*HALO)        // 14
#define NHP   (HDW*HDH)            // 476
#define NT    256
#define NW    (NT/32)              // 8
#define F4    (CCH/4)              // 48

// pooled[pix*2+0]=avg, [pix*2+1]=max  (3.2 MB, L2-resident)
__device__ float g_pooled[NPIX * 2];

__device__ __forceinline__ float hsum(float4 v) { return (v.x + v.y) + (v.z + v.w); }
__device__ __forceinline__ float hmax(float4 v) { return fmaxf(fmaxf(v.x, v.y), fmaxf(v.z, v.w)); }

// ---------------- Kernel A: channel avg/max, 2 pixels per warp ----------------
// Default cache policy on x: we WANT the chunk resident in L2 for apply.
__global__ __launch_bounds__(NT, 8)
void reduce_kernel(const float* __restrict__ x, int pair0)
{
    const int lane = threadIdx.x & 31;
    const int pair = pair0 + blockIdx.x * NW + (threadIdx.x >> 5);

    const float4* p = reinterpret_cast<const float4*>(x + (size_t)pair * 2 * CCH);
    float4 a0 = p[lane];           // f4 [0,32)   -> pixel 0
    float4 a1 = p[32 + lane];      // f4 [32,64)  -> px0 (lane<16) / px1 (lane>=16)
    float4 a2 = p[64 + lane];      // f4 [64,96)  -> pixel 1

    float s0 = hsum(a0), m0 = hmax(a0);
    float s1 = hsum(a2), m1 = hmax(a2);
    float sm = hsum(a1), mm = hmax(a1);
    if (lane < 16) { s0 += sm; m0 = fmaxf(m0, mm); }
    else           { s1 += sm; m1 = fmaxf(m1, mm); }

    #pragma unroll
    for (int o = 16; o > 0; o >>= 1) {
        s0 += __shfl_xor_sync(0xffffffffu, s0, o);
        s1 += __shfl_xor_sync(0xffffffffu, s1, o);
        m0  = fmaxf(m0, __shfl_xor_sync(0xffffffffu, m0, o));
        m1  = fmaxf(m1, __shfl_xor_sync(0xffffffffu, m1, o));
    }
    if (lane == 0) {
        float4 r = make_float4(s0 * (1.0f / CCH), m0, s1 * (1.0f / CCH), m1);
        *reinterpret_cast<float4*>(&g_pooled[(size_t)pair * 4]) = r;
    }
}

// ---------------- Kernel B: conv + sigmoid + apply (fused) ----------------
__global__ __launch_bounds__(NT, 8)
void apply_kernel(const float* __restrict__ x,
                  const float* __restrict__ w,
                  float* __restrict__ out,
                  int b0)
{
    __shared__ float s_avg[NHP];
    __shared__ float s_max[NHP];
    __shared__ float s_att[TW*TH];
    __shared__ float s_w[98];

    const int tid = threadIdx.x;
    if (tid < 98) s_w[tid] = w[tid];

    const int TPX = IMG / TW;                // 4
    const int TPY = IMG / TH;                // 14
    int bidx = blockIdx.x;
    int b    = b0 + bidx / (TPX*TPY);
    int tr   = bidx % (TPX*TPY);
    int ty0  = (tr / TPX) * TH;
    int tx0  = (tr % TPX) * TW;

    // ---- Phase 1: load pooled halo (tiny, L2-hot) ----
    for (int p = tid; p < NHP; p += NT) {
        int hy = ty0 + p / HDW - HALO;
        int wx = tx0 + p % HDW - HALO;
        float a = 0.f, m = 0.f;
        if (hy >= 0 && hy < IMG && wx >= 0 && wx < IMG) {
            size_t pix = ((size_t)b * IMG + hy) * IMG + wx;
            float2 r = *reinterpret_cast<const float2*>(&g_pooled[pix * 2]);
            a = r.x; m = r.y;
        }
        s_avg[p] = a;
        s_max[p] = m;
    }
    __syncthreads();

    // ---- Phase 2: 7x7 conv (cross-correlation) + sigmoid ----
    if (tid < TW*TH) {
        int oy = tid / TW, ox = tid % TW;
        float acc = 0.f;
        #pragma unroll
        for (int kh = 0; kh < 7; kh++) {
            #pragma unroll
            for (int kw = 0; kw < 7; kw++) {
                int p = (oy + kh) * HDW + (ox + kw);
                acc = fmaf(s_avg[p], s_w[(kh*7 + kw)*2 + 0], acc);
                acc = fmaf(s_max[p], s_w[(kh*7 + kw)*2 + 1], acc);
            }
        }
        s_att[tid] = 1.0f / (1.0f + __expf(-acc));
    }
    __syncthreads();

    // ---- Phase 3: out = x * att; x read should hit L2 (loaded by reduce),
    //      out written streaming so it doesn't evict the next x chunk ----
    // total4 = 28*8*48 = 10752 = 21 * (NT*2) -> no remainder
    const int total4 = TW*TH*F4;
    #pragma unroll 1
    for (int k = tid; k < total4; k += NT*2) {
        float4 v[2]; float a[2]; size_t g[2];
        #pragma unroll
        for (int u = 0; u < 2; u++) {
            int kk = k + u*NT;
            int pt = kk / F4;
            int c4 = kk - pt * F4;
            int oy = pt / TW, ox = pt - oy * TW;
            g[u] = (((size_t)b * IMG + (ty0 + oy)) * IMG + (tx0 + ox)) * CCH + (size_t)c4 * 4;
            v[u] = *reinterpret_cast<const float4*>(x + g[u]);
            a[u] = s_att[pt];
        }
        #pragma unroll
        for (int u = 0; u < 2; u++) {
            float4 r = v[u]; float s = a[u];
            r.x *= s; r.y *= s; r.z *= s; r.w *= s;
            __stcs(reinterpret_cast<float4*>(out + g[u]), r);
        }
    }
}

extern "C" void kernel_launch(void* const* d_in, const int* in_sizes, int n_in,
                              void* d_out, int out_size)
{
    const float* x = (const float*)d_in[0];
    const float* w = (const float*)d_in[1];
    float* out = (float*)d_out;

    const int TPX = IMG / TW, TPY = IMG / TH;        // 4, 14
    const int RBLK_G = PAIRS_G / NW;                 // 6272
    const int ABLK_G = GIMG * TPX * TPY;             // 448

    // Sequential per-group pipeline on ONE stream: reduce(g) pulls the
    // 77 MB x-chunk into L2; apply(g) re-reads it from L2 immediately.
    for (int g = 0; g < NGRP; g++) {
        reduce_kernel<<<RBLK_G, NT>>>(x, g * PAIRS_G);
        apply_kernel<<<ABLK_G, NT>>>(x, w, out, g * GIMG);
    }
}

// round 11
// speedup vs baseline: 1.1404x; 1.1054x over previous
#include <cuda_runtime.h>
#include <math.h>

#define IMG   112
#define CCH   192
#define NPIX  (32*IMG*IMG)         // 401408 pixels
#define GIMG  8                    // images per group (77 MB x-chunk < 126 MB L2)
#define NGRP  (32/GIMG)            // 4 groups
#define PAIRS_G (GIMG*IMG*IMG/2)   // 50176 pixel-pairs per group
#define TW    28
#define TH    4
#define HALO  3
#define HDW   (TW + 2*HALO)        // 34
#define HDH   (TH + 2*HALO)        // 10
#define NHP   (HDW*HDH)            // 340
#define NT    256
#define NW    (NT/32)              // 8
#define F4    (CCH/4)              // 48

// pooled[pix*2+0]=avg, [pix*2+1]=max  (3.2 MB, L2-resident)
__device__ float g_pooled[NPIX * 2];

__device__ __forceinline__ float hsum(float4 v) { return (v.x + v.y) + (v.z + v.w); }
__device__ __forceinline__ float hmax(float4 v) { return fmaxf(fmaxf(v.x, v.y), fmaxf(v.z, v.w)); }

// ---------------- Kernel A: channel avg/max, 2 pixels per warp ----------------
// Default cache policy on x: we WANT the chunk resident in L2 for apply.
__global__ __launch_bounds__(NT, 8)
void reduce_kernel(const float* __restrict__ x, int pair0)
{
    const int lane = threadIdx.x & 31;
    const int pair = pair0 + blockIdx.x * NW + (threadIdx.x >> 5);

    const float4* p = reinterpret_cast<const float4*>(x + (size_t)pair * 2 * CCH);
    float4 a0 = p[lane];           // f4 [0,32)   -> pixel 0
    float4 a1 = p[32 + lane];      // f4 [32,64)  -> px0 (lane<16) / px1 (lane>=16)
    float4 a2 = p[64 + lane];      // f4 [64,96)  -> pixel 1

    float s0 = hsum(a0), m0 = hmax(a0);
    float s1 = hsum(a2), m1 = hmax(a2);
    float sm = hsum(a1), mm = hmax(a1);
    if (lane < 16) { s0 += sm; m0 = fmaxf(m0, mm); }
    else           { s1 += sm; m1 = fmaxf(m1, mm); }

    #pragma unroll
    for (int o = 16; o > 0; o >>= 1) {
        s0 += __shfl_xor_sync(0xffffffffu, s0, o);
        s1 += __shfl_xor_sync(0xffffffffu, s1, o);
        m0  = fmaxf(m0, __shfl_xor_sync(0xffffffffu, m0, o));
        m1  = fmaxf(m1, __shfl_xor_sync(0xffffffffu, m1, o));
    }
    if (lane == 0) {
        float4 r = make_float4(s0 * (1.0f / CCH), m0, s1 * (1.0f / CCH), m1);
        *reinterpret_cast<float4*>(&g_pooled[(size_t)pair * 4]) = r;
    }
}

// ---------------- Kernel B: conv + sigmoid + apply (fused) ----------------
__global__ __launch_bounds__(NT, 8)
void apply_kernel(const float* __restrict__ x,
                  const float* __restrict__ w,
                  float* __restrict__ out,
                  int b0)
{
    __shared__ float s_avg[NHP];
    __shared__ float s_max[NHP];
    __shared__ float s_att[TW*TH];
    __shared__ float s_w[98];

    const int tid = threadIdx.x;
    if (tid < 98) s_w[tid] = w[tid];

    const int TPX = IMG / TW;                // 4
    const int TPY = IMG / TH;                // 28
    int bidx = blockIdx.x;
    int b    = b0 + bidx / (TPX*TPY);
    int tr   = bidx % (TPX*TPY);
    int ty0  = (tr / TPX) * TH;
    int tx0  = (tr % TPX) * TW;

    // ---- Phase 1: load pooled halo (tiny, L2-hot) ----
    for (int p = tid; p < NHP; p += NT) {
        int hy = ty0 + p / HDW - HALO;
        int wx = tx0 + p % HDW - HALO;
        float a = 0.f, m = 0.f;
        if (hy >= 0 && hy < IMG && wx >= 0 && wx < IMG) {
            size_t pix = ((size_t)b * IMG + hy) * IMG + wx;
            float2 r = *reinterpret_cast<const float2*>(&g_pooled[pix * 2]);
            a = r.x; m = r.y;
        }
        s_avg[p] = a;
        s_max[p] = m;
    }
    __syncthreads();

    // ---- Phase 2: 7x7 conv (cross-correlation) + sigmoid ----
    if (tid < TW*TH) {
        int oy = tid / TW, ox = tid % TW;
        float acc = 0.f;
        #pragma unroll
        for (int kh = 0; kh < 7; kh++) {
            #pragma unroll
            for (int kw = 0; kw < 7; kw++) {
                int p = (oy + kh) * HDW + (ox + kw);
                acc = fmaf(s_avg[p], s_w[(kh*7 + kw)*2 + 0], acc);
                acc = fmaf(s_max[p], s_w[(kh*7 + kw)*2 + 1], acc);
            }
        }
        s_att[tid] = 1.0f / (1.0f + __expf(-acc));
    }
    __syncthreads();

    // ---- Phase 3: out = x * att; x reads hit L2 (loaded by reduce),
    //      out written streaming so it doesn't evict x ----
    // total4 = 28*4*48 = 5376 = 7 * (NT*3) -> no remainder
    const int total4 = TW*TH*F4;
    #pragma unroll 1
    for (int k = tid; k < total4; k += NT*3) {
        float4 v[3]; float a[3]; size_t g[3];
        #pragma unroll
        for (int u = 0; u < 3; u++) {
            int kk = k + u*NT;
            int pt = kk / F4;
            int c4 = kk - pt * F4;
            int oy = pt / TW, ox = pt - oy * TW;
            g[u] = (((size_t)b * IMG + (ty0 + oy)) * IMG + (tx0 + ox)) * CCH + (size_t)c4 * 4;
            v[u] = *reinterpret_cast<const float4*>(x + g[u]);
            a[u] = s_att[pt];
        }
        #pragma unroll
        for (int u = 0; u < 3; u++) {
            float4 r = v[u]; float s = a[u];
            r.x *= s; r.y *= s; r.z *= s; r.w *= s;
            __stcs(reinterpret_cast<float4*>(out + g[u]), r);
        }
    }
}

extern "C" void kernel_launch(void* const* d_in, const int* in_sizes, int n_in,
                              void* d_out, int out_size)
{
    const float* x = (const float*)d_in[0];
    const float* w = (const float*)d_in[1];
    float* out = (float*)d_out;

    const int TPX = IMG / TW, TPY = IMG / TH;        // 4, 28
    const int RBLK_G = PAIRS_G / NW;                 // 6272
    const int ABLK_G = GIMG * TPX * TPY;             // 896

    // Sequential per-group pipeline on ONE stream: reduce(g) pulls the
    // 77 MB x-chunk into L2; apply(g) re-reads it from L2.
    for (int g = 0; g < NGRP; g++) {
        reduce_kernel<<<RBLK_G, NT>>>(x, g * PAIRS_G);
        apply_kernel<<<ABLK_G, NT>>>(x, w, out, g * GIMG);
    }
}